// round 5
// baseline (speedup 1.0000x reference)
#include <cuda_runtime.h>
#include <cstdint>

// x: (128, 1, 28, 28) f32  -> out: (128, 785, 28, 28) f32
// out[b,0,:]   = new_pv(x[b])
// out[b,1+i,:] = new_e(x[b,i]) at flat pos i, else 0
static constexpr unsigned B     = 128;
static constexpr unsigned HW    = 784;               // 28*28
static constexpr unsigned CPB   = 785u * 784u;       // floats per batch
static constexpr unsigned CPB4  = CPB / 4u;          // float4 per batch = 153,860
static constexpr unsigned CPCH  = 49u;               // 16-float chunks per channel (784/16)
static constexpr unsigned CHPB  = 785u * CPCH;       // chunks per batch = 38,465

__device__ __forceinline__ float pv_map(float pv) {
    const float eps = 0.1f;
    bool low  = pv < eps;
    bool high = pv > 1.0f - eps;
    return low  ? (pv + eps) * 0.5f
         : high ? (pv + (1.0f - eps)) * 0.5f
         :        pv;
}

__device__ __forceinline__ float e_map(float pv) {
    const float eps = 0.1f;
    bool low  = pv < eps;
    bool high = pv > 1.0f - eps;
    return low  ? (eps + pv) * 0.5f
         : high ? ((1.0f - pv) + eps) * 0.5f
         :        eps;
}

// One thread = one 64-byte chunk (4x float4). 784 % 16 == 0, so a chunk
// never crosses a channel boundary: one channel decision per 64B.
__global__ void fused_kernel(const float* __restrict__ x,
                             float4* __restrict__ out) {
    unsigned t = blockIdx.x * blockDim.x + threadIdx.x;   // chunk within batch
    if (t >= CHPB) return;
    unsigned b = blockIdx.y;

    float4* dst = out + (size_t)b * CPB4 + (size_t)t * 4u;
    const float* xb = x + b * HW;

    unsigned c = t / CPCH;                 // channel  (const-div -> IMAD.HI)
    unsigned r = (t - c * CPCH) * 16u;     // float offset within channel

    if (c == 0u) {
        // Channel 0: 16 contiguous pv-mapped inputs.
        const float4* xs = reinterpret_cast<const float4*>(xb) + (r >> 2);
        #pragma unroll
        for (int k = 0; k < 4; k++) {
            float4 xv = xs[k];
            float4 v;
            v.x = pv_map(xv.x);
            v.y = pv_map(xv.y);
            v.z = pv_map(xv.z);
            v.w = pv_map(xv.w);
            dst[k] = v;
        }
    } else {
        // Build 16 floats in registers (all zero except maybe one), store 4x f4.
        float vals[16];
        #pragma unroll
        for (int k = 0; k < 16; k++) vals[k] = 0.f;

        unsigned i = c - 1u;               // diagonal position for this channel
        unsigned d = i - r;                // in-chunk offset if < 16
        if (d < 16u) {
            vals[d] = e_map(xb[i]);
        }

        #pragma unroll
        for (int k = 0; k < 4; k++) {
            dst[k] = make_float4(vals[4*k+0], vals[4*k+1], vals[4*k+2], vals[4*k+3]);
        }
    }
}

extern "C" void kernel_launch(void* const* d_in, const int* in_sizes, int n_in,
                              void* d_out, int out_size) {
    const float* x = (const float*)d_in[0];
    float4* out = (float4*)d_out;

    const int threads = 256;
    dim3 grid((CHPB + threads - 1) / threads, B);   // (151, 128)
    fused_kernel<<<grid, threads>>>(x, out);
}

// round 6
// speedup vs baseline: 1.0015x; 1.0015x over previous
#include <cuda_runtime.h>
#include <cstdint>

// x: (128, 1, 28, 28) f32  -> out: (128, 785, 28, 28) f32
// out[b,0,:]   = new_pv(x[b])
// out[b,1+i,:] = new_e(x[b,i]) at flat pos i, else 0
static constexpr unsigned B     = 128;
static constexpr unsigned HW    = 784;               // 28*28
static constexpr unsigned CPB   = 785u * 784u;       // floats per batch
static constexpr unsigned CPB4  = CPB / 4u;          // float4 per batch = 153,860
static constexpr unsigned CPCH  = 49u;               // 16-float chunks per channel (784/16)
static constexpr unsigned CHPB  = 785u * CPCH;       // chunks per batch = 38,465

__device__ __forceinline__ float pv_map(float pv) {
    const float eps = 0.1f;
    bool low  = pv < eps;
    bool high = pv > 1.0f - eps;
    return low  ? (pv + eps) * 0.5f
         : high ? (pv + (1.0f - eps)) * 0.5f
         :        pv;
}

__device__ __forceinline__ float e_map(float pv) {
    const float eps = 0.1f;
    bool low  = pv < eps;
    bool high = pv > 1.0f - eps;
    return low  ? (eps + pv) * 0.5f
         : high ? ((1.0f - pv) + eps) * 0.5f
         :        eps;
}

// One thread = one 64-byte chunk (4x float4). 784 % 16 == 0, so a chunk
// never crosses a channel boundary: one channel decision per 64B.
// NO dynamically-indexed arrays anywhere (they spill to local memory).
__global__ void fused_kernel(const float* __restrict__ x,
                             float4* __restrict__ out) {
    unsigned t = blockIdx.x * blockDim.x + threadIdx.x;   // chunk within batch
    if (t >= CHPB) return;
    unsigned b = blockIdx.y;

    float4* dst = out + (size_t)b * CPB4 + (size_t)t * 4u;
    const float* xb = x + b * HW;

    unsigned c = t / CPCH;                 // channel  (const-div -> IMAD.HI)
    unsigned r = (t - c * CPCH) * 16u;     // float offset within channel

    if (c == 0u) {
        // Channel 0: 16 contiguous pv-mapped inputs.
        const float4* xs = reinterpret_cast<const float4*>(xb) + (r >> 2);
        #pragma unroll
        for (int k = 0; k < 4; k++) {
            float4 xv = xs[k];
            float4 v;
            v.x = pv_map(xv.x);
            v.y = pv_map(xv.y);
            v.z = pv_map(xv.z);
            v.w = pv_map(xv.w);
            dst[k] = v;
        }
    } else {
        // 16 zeros except (maybe) one diagonal element, composed with selects.
        unsigned i = c - 1u;               // diagonal position for this channel
        unsigned d = i - r;                // in-chunk offset if < 16 (unsigned wrap ok)
        float ev = (d < 16u) ? e_map(xb[i]) : 0.f;

        #pragma unroll
        for (int k = 0; k < 4; k++) {
            float4 v;
            v.x = (d == (unsigned)(4 * k + 0)) ? ev : 0.f;
            v.y = (d == (unsigned)(4 * k + 1)) ? ev : 0.f;
            v.z = (d == (unsigned)(4 * k + 2)) ? ev : 0.f;
            v.w = (d == (unsigned)(4 * k + 3)) ? ev : 0.f;
            dst[k] = v;
        }
    }
}

extern "C" void kernel_launch(void* const* d_in, const int* in_sizes, int n_in,
                              void* d_out, int out_size) {
    const float* x = (const float*)d_in[0];
    float4* out = (float4*)d_out;

    const int threads = 256;
    dim3 grid((CHPB + threads - 1) / threads, B);   // (151, 128)
    fused_kernel<<<grid, threads>>>(x, out);
}

// round 9
// speedup vs baseline: 1.7500x; 1.7474x over previous
#include <cuda_runtime.h>
#include <cstdint>

// x: (128, 1, 28, 28) f32  -> out: (128, 785, 28, 28) f32
// out[b,0,:]   = new_pv(x[b])
// out[b,1+i,:] = new_e(x[b,i]) at flat pos i, else 0
static constexpr unsigned B     = 128;
static constexpr unsigned HW    = 784;               // floats per channel
static constexpr unsigned HW4   = 196;               // float4 per channel
static constexpr unsigned CPB4  = 785u * 196u;       // float4 per batch = 153,860
static constexpr unsigned F4_PER_BLOCK = 2048;       // 32KB contiguous per block
static constexpr unsigned ITERS = 8;                 // 2048 / 256

__device__ __forceinline__ float pv_map(float pv) {
    const float eps = 0.1f;
    bool low  = pv < eps;
    bool high = pv > 1.0f - eps;
    return low  ? (pv + eps) * 0.5f
         : high ? (pv + (1.0f - eps)) * 0.5f
         :        pv;
}

__device__ __forceinline__ float e_map(float pv) {
    const float eps = 0.1f;
    bool low  = pv < eps;
    bool high = pv > 1.0f - eps;
    return low  ? (eps + pv) * 0.5f
         : high ? ((1.0f - pv) + eps) * 0.5f
         :        eps;
}

// Warp-coalesced fused kernel: thread stores 8 float4s at 4KB (256-f4) stride,
// so every warp STG.128 covers 512B contiguous (4 full 128B wavefronts).
__global__ void fused_kernel(const float* __restrict__ x,
                             float4* __restrict__ out) {
    const unsigned b = blockIdx.y;
    unsigned j4 = blockIdx.x * F4_PER_BLOCK + threadIdx.x;  // f4 index in batch

    const float* xb = x + b * HW;
    float4* ob = out + (unsigned long long)b * (unsigned long long)CPB4;

    #pragma unroll
    for (unsigned j = 0; j < ITERS; j++, j4 += 256u) {
        bool in_range = (j4 < CPB4);
        if (in_range) {
            unsigned c  = j4 / HW4;            // channel (reciprocal-mul div)
            unsigned r4 = j4 - c * HW4;        // f4 offset within channel
            unsigned d  = c - 1u - 4u * r4;    // diag offset in this window (wraps)

            float4 v = make_float4(0.f, 0.f, 0.f, 0.f);
            if (c == 0u) {
                // channel 0: pv map of 4 contiguous inputs (rare: 196/153860)
                float4 xv = reinterpret_cast<const float4*>(xb)[r4];
                v.x = pv_map(xv.x);
                v.y = pv_map(xv.y);
                v.z = pv_map(xv.z);
                v.w = pv_map(xv.w);
            } else if (d < 4u) {
                // diagonal element lands in this float4 (rare: 1/196)
                float ev = e_map(xb[c - 1u]);
                v.x = (d == 0u) ? ev : 0.f;
                v.y = (d == 1u) ? ev : 0.f;
                v.z = (d == 2u) ? ev : 0.f;
                v.w = (d == 3u) ? ev : 0.f;
            }
            ob[j4] = v;
        }
    }
}

extern "C" void kernel_launch(void* const* d_in, const int* in_sizes, int n_in,
                              void* d_out, int out_size) {
    const float* x = (const float*)d_in[0];
    float4* out = (float4*)d_out;

    const int threads = 256;
    dim3 grid((CPB4 + F4_PER_BLOCK - 1) / F4_PER_BLOCK, B);  // (76, 128)
    fused_kernel<<<grid, threads>>>(x, out);
}

// round 10
// speedup vs baseline: 1.8174x; 1.0385x over previous
#include <cuda_runtime.h>
#include <cstdint>

// x: (128, 1, 28, 28) f32  -> out: (128, 785, 28, 28) f32
// out[b,0,:]   = new_pv(x[b])
// out[b,1+i,:] = new_e(x[b,i]) at flat pos i, else 0
static constexpr unsigned B     = 128;
static constexpr unsigned HW    = 784;               // floats per channel
static constexpr unsigned HW4   = 196;               // float4 per channel
static constexpr unsigned CPB4  = 785u * 196u;       // float4 per batch = 153,860
static constexpr unsigned F4_PER_BLOCK = 2048;       // 32KB contiguous per block
static constexpr unsigned ITERS = 8;                 // 2048 / 256
static constexpr unsigned STEP  = 256;               // threads per block

__device__ __forceinline__ float pv_map(float pv) {
    const float eps = 0.1f;
    bool low  = pv < eps;
    bool high = pv > 1.0f - eps;
    return low  ? (pv + eps) * 0.5f
         : high ? (pv + (1.0f - eps)) * 0.5f
         :        pv;
}

__device__ __forceinline__ float e_map(float pv) {
    const float eps = 0.1f;
    bool low  = pv < eps;
    bool high = pv > 1.0f - eps;
    return low  ? (eps + pv) * 0.5f
         : high ? ((1.0f - pv) + eps) * 0.5f
         :        eps;
}

// Warp-coalesced fused kernel. Thread stores 8 float4s at 4KB (256-f4) stride:
// every warp STG.128 covers 512B contiguous. (c, r4) tracked incrementally —
// the only integer division is in the prologue.
__global__ void fused_kernel(const float* __restrict__ x,
                             float4* __restrict__ out) {
    const unsigned b = blockIdx.y;
    unsigned j4 = blockIdx.x * F4_PER_BLOCK + threadIdx.x;  // f4 index in batch

    const float* xb = x + b * HW;
    float4* ob = out + (unsigned long long)b * (unsigned long long)CPB4;

    // Prologue: one division, then incremental updates.
    unsigned c  = j4 / HW4;               // channel
    unsigned r4 = j4 - c * HW4;           // f4 offset within channel

    #pragma unroll
    for (unsigned j = 0; j < ITERS; j++) {
        if (j4 < CPB4) {
            unsigned d = c - 1u - 4u * r4;     // diag offset in window (wraps)

            float4 v = make_float4(0.f, 0.f, 0.f, 0.f);
            if (c == 0u) {
                // channel 0: pv map of 4 contiguous inputs (only block x==0)
                float4 xv = reinterpret_cast<const float4*>(xb)[r4];
                v.x = pv_map(xv.x);
                v.y = pv_map(xv.y);
                v.z = pv_map(xv.z);
                v.w = pv_map(xv.w);
            } else if (d < 4u) {
                // diagonal element lands in this float4 (1 in 196)
                float ev = e_map(xb[c - 1u]);
                v.x = (d == 0u) ? ev : 0.f;
                v.y = (d == 1u) ? ev : 0.f;
                v.z = (d == 2u) ? ev : 0.f;
                v.w = (d == 3u) ? ev : 0.f;
            }
            __stcs(ob + j4, v);                // streaming store, evict-first
        }
        // Advance by 256 f4: c += 1, r4 += 60, with at most one wrap.
        j4 += STEP;
        c  += 1u;
        r4 += STEP - HW4;                      // +60
        if (r4 >= HW4) { r4 -= HW4; c += 1u; }
    }
}

extern "C" void kernel_launch(void* const* d_in, const int* in_sizes, int n_in,
                              void* d_out, int out_size) {
    const float* x = (const float*)d_in[0];
    float4* out = (float4*)d_out;

    const int threads = 256;
    dim3 grid((CPB4 + F4_PER_BLOCK - 1) / F4_PER_BLOCK, B);  // (76, 128)
    fused_kernel<<<grid, threads>>>(x, out);
}